// round 13
// baseline (speedup 1.0000x reference)
#include <cuda_runtime.h>
#include <cuda_bf16.h>
#include <math.h>

// Problem constants
#define Bc 128
#define Nc 128
#define Ec 64
#define TYPEC 201   // TYPE_NUM+1
#define RELC  51    // REL_NUM+1

#define NTHR 384
#define BAR_B() asm volatile("bar.sync 1, 128;" ::: "memory")

typedef unsigned long long ull;

// ---- Blackwell packed f32x2 helpers (fma/pack/unpack only) ----
__device__ __forceinline__ ull f2fma(ull a, ull b, ull c) {
    ull d; asm("fma.rn.f32x2 %0, %1, %2, %3;" : "=l"(d) : "l"(a), "l"(b), "l"(c)); return d;
}
__device__ __forceinline__ ull packf2(float lo, float hi) {
    ull d; asm("mov.b64 %0, {%1, %2};" : "=l"(d) : "f"(lo), "f"(hi)); return d;
}
__device__ __forceinline__ float2 unpackf2(ull v) {
    float lo, hi; asm("mov.b64 {%0, %1}, %2;" : "=f"(lo), "=f"(hi) : "l"(v));
    return make_float2(lo, hi);
}

// Precomputed batch-independent tables
__device__ float g_typeproj[TYPEC * 192];
__device__ float g_relproj[RELC * 64];

struct GParams {
    const int*   node_slice;
    const int*   type_slice;
    const float* distance;
    const int*   rel_matrix;
    const int*   input_length;
    const float* emb_table;
    const float* type_table;
    const float* rel_table;
    const float* W_in; const float* b_in;
    const float* Wr;   const float* br;
    const float* Wz;   const float* bz;
    const float* Wt;   const float* bt;
    const float* W_co; const float* b_co;
    const float* W1;   const float* b1;
    const float* W2;   const float* b2;
    const float* W3;   const float* b3;
    const float* W4;   const float* b4;
    float* out;
};

// ---------------------------------------------------------------------------
__global__ void ggnn_pre(GParams p) {
    int blk = blockIdx.x;
    int t = threadIdx.x;
    if (blk < TYPEC) {
        if (t < 192) {
            int gate = t >> 6, e = t & 63;
            const float* Wg = (gate == 0) ? p.Wr : ((gate == 1) ? p.Wz : p.Wt);
            const float* bg = (gate == 0) ? p.br : ((gate == 1) ? p.bz : p.bt);
            float acc = bg[e];
            #pragma unroll
            for (int k = 0; k < 32; k++)
                acc += p.type_table[blk * 32 + k] * Wg[k * 64 + e];
            g_typeproj[blk * 192 + t] = acc;
        }
    } else {
        if (t < 64) {
            for (int v = 0; v < RELC; v++) {
                float acc = 0.f;
                #pragma unroll
                for (int k = 0; k < 32; k++)
                    acc += p.rel_table[v * 32 + k] * p.W_in[(64 + k) * 64 + t];
                g_relproj[v * 64 + t] = acc;
            }
        }
    }
}

// ---------------------------------------------------------------------------
// Shared layout (float offsets) — identical to R10
// ---------------------------------------------------------------------------
#define SM_HD    0        // 8192 : (hidden@W_h + b_in) * disc[row]
#define SM_HID   8192     // 8192 : raw hidden state
#define SM_NP    16384    // 24576
#define SM_RP    40960    // 3264 (row 0 = +1e30 sentinel), pad to 3328
#define SM_DISC  44288    // 128
#define SM_PBUF  44416    // 2 * 9 * 64 = 1152 (8 A slots + 1 corr slot)
#define SM_DP    45568    // 64
#define SM_RD    45632    // 64 : r * dis_pre
#define SM_Z     45696    // 64 : z gate scratch
#define SM_NR    45760    // 64
#define SM_BIN   45824    // 64
#define SM_RV    45888    // 3*128 ints : rel row ring
#define SM_TV    46272    // 128 ints
#define SM_CORRV 46400    // 3 ints (pad 64)
#define SM_FIN   46464    // 768
#define SM_STAGE 47232    // 8192 (init GEMM staging)
#define SMEM_FLOATS 55424

__global__ void __launch_bounds__(NTHR, 1) ggnn_main(GParams p) {
    extern __shared__ float S[];
    const int t = threadIdx.x;
    const int b = blockIdx.x;
    int* rvs = (int*)&S[SM_RV];
    int* tvs = (int*)&S[SM_TV];
    int* corrv = (int*)&S[SM_CORRV];
    const int len = p.input_length[b];
    const int* relrow = p.rel_matrix + (long long)b * Nc * Nc;

    // ---------------- init gathers ----------------
    {
        const float4* emb4 = (const float4*)p.emb_table;
        float4* hid4 = (float4*)&S[SM_HID];
        for (int idx = t; idx < Nc * 16; idx += NTHR) {
            int j = idx >> 4, q = idx & 15;
            long long nd = p.node_slice[b * Nc + j];
            hid4[idx] = emb4[nd * 16 + q];
        }
    }
    if (t < 128) {
        S[SM_DISC + t] = -0.1f * p.distance[b * Nc + t];
        tvs[t] = p.type_slice[b * Nc + t];
        rvs[t] = (t < len) ? relrow[t] : 0;      // ring slot 0, len-masked
    }
    for (int idx = t; idx < RELC * 64; idx += NTHR) S[SM_RP + idx] = g_relproj[idx];
    if (t < 64) {
        S[SM_RP + t] = 1e30f;                    // sentinel row: rv==0 -> s ~ -1e29
        S[SM_BIN + t] = p.b_in[t];
        S[SM_PBUF + 512 + t] = -1e30f;           // corr slot of buffer 0
    }

    // ---- persistent PACKED gate weights in registers (group B: t>=256) ----
    ull wR2[16], wZ2[16], wT2[16], wH2[16];
    if (t >= 256) {
        int u = t - 256;
        int e = u >> 1, half = u & 1;
        int kb = 96 + half * 32;
        #pragma unroll
        for (int q = 0; q < 16; q++) {
            wR2[q] = packf2(p.Wr[(kb + 2 * q) * 64 + e], p.Wr[(kb + 2 * q + 1) * 64 + e]);
            wZ2[q] = packf2(p.Wz[(kb + 2 * q) * 64 + e], p.Wz[(kb + 2 * q + 1) * 64 + e]);
            wT2[q] = packf2(p.Wt[(kb + 2 * q) * 64 + e], p.Wt[(kb + 2 * q + 1) * 64 + e]);
            wH2[q] = packf2(p.W_in[(half * 32 + 2 * q) * 64 + e],
                            p.W_in[(half * 32 + 2 * q + 1) * 64 + e]);
        }
    }
    __syncthreads();

    // ---------------- HD init: HD = (hidden @ W_h + b_in) * disc ----------------
    for (int idx = t; idx < 4096; idx += NTHR) S[SM_STAGE + idx] = p.W_in[idx];
    __syncthreads();
    for (int x = t; x < 512; x += NTHR) {
        int j0 = (x >> 4) << 2, e0 = (x & 15) << 2;
        float acc[4][4];
        #pragma unroll
        for (int m = 0; m < 4; m++)
            #pragma unroll
            for (int n = 0; n < 4; n++) acc[m][n] = S[SM_BIN + e0 + n];
        #pragma unroll 4
        for (int k = 0; k < 64; k++) {
            float4 w = *(const float4*)&S[SM_STAGE + k * 64 + e0];
            #pragma unroll
            for (int m = 0; m < 4; m++) {
                float h = S[SM_HID + (j0 + m) * 64 + k];
                acc[m][0] += h * w.x; acc[m][1] += h * w.y;
                acc[m][2] += h * w.z; acc[m][3] += h * w.w;
            }
        }
        #pragma unroll
        for (int m = 0; m < 4; m++) {
            float d = S[SM_DISC + j0 + m];
            #pragma unroll
            for (int n = 0; n < 4; n++)
                S[SM_HD + (j0 + m) * 64 + e0 + n] = acc[m][n] * d;
        }
    }
    __syncthreads();

    // -------- now_part: typeproj[tv] + node_emb @ Wg[32:96] --------
    for (int idx = t; idx < 8192; idx += NTHR) {
        int k = idx >> 7, c = idx & 127;
        S[SM_STAGE + idx] = (c < 64) ? p.Wr[(32 + k) * 64 + c]
                                     : p.Wz[(32 + k) * 64 + (c - 64)];
    }
    __syncthreads();
    for (int x = t; x < 1024; x += NTHR) {
        int i0 = (x >> 5) << 2, c0 = (x & 31) << 2;
        float acc[4][4];
        #pragma unroll
        for (int m = 0; m < 4; m++) {
            const float* tp = &g_typeproj[tvs[i0 + m] * 192 + c0];
            acc[m][0] = tp[0]; acc[m][1] = tp[1]; acc[m][2] = tp[2]; acc[m][3] = tp[3];
        }
        #pragma unroll 4
        for (int k = 0; k < 64; k++) {
            float4 w = *(const float4*)&S[SM_STAGE + k * 128 + c0];
            #pragma unroll
            for (int m = 0; m < 4; m++) {
                float h = S[SM_HID + (i0 + m) * 64 + k];
                acc[m][0] += h * w.x; acc[m][1] += h * w.y;
                acc[m][2] += h * w.z; acc[m][3] += h * w.w;
            }
        }
        #pragma unroll
        for (int m = 0; m < 4; m++)
            #pragma unroll
            for (int n = 0; n < 4; n++)
                S[SM_NP + (i0 + m) * 192 + c0 + n] = acc[m][n];
    }
    __syncthreads();
    for (int idx = t; idx < 4096; idx += NTHR) {
        int k = idx >> 6, e = idx & 63;
        S[SM_STAGE + idx] = p.Wt[(32 + k) * 64 + e];
    }
    __syncthreads();
    for (int x = t; x < 512; x += NTHR) {
        int i0 = (x >> 4) << 2, e0 = (x & 15) << 2;
        float acc[4][4];
        #pragma unroll
        for (int m = 0; m < 4; m++) {
            const float* tp = &g_typeproj[tvs[i0 + m] * 192 + 128 + e0];
            acc[m][0] = tp[0]; acc[m][1] = tp[1]; acc[m][2] = tp[2]; acc[m][3] = tp[3];
        }
        #pragma unroll 4
        for (int k = 0; k < 64; k++) {
            float4 w = *(const float4*)&S[SM_STAGE + k * 64 + e0];
            #pragma unroll
            for (int m = 0; m < 4; m++) {
                float h = S[SM_HID + (i0 + m) * 64 + k];
                acc[m][0] += h * w.x; acc[m][1] += h * w.y;
                acc[m][2] += h * w.z; acc[m][3] += h * w.w;
            }
        }
        #pragma unroll
        for (int m = 0; m < 4; m++)
            #pragma unroll
            for (int n = 0; n < 4; n++)
                S[SM_NP + (i0 + m) * 192 + 128 + e0 + n] = acc[m][n];
    }
    __syncthreads();

    // ---------------- pipelined scan ----------------
    // iter i: A (t<256, 8 warps) computes max_j f32x2-fma(rp, d, hd) partials
    // for step i+1, with its 8 HD rows CACHED IN REGISTERS (refreshing the one
    // row B rewrote last iter); B (t>=256, 4 warps): 9-max+clamp -> r,z ->
    // hhat+update -> HD+corr.
    const int lane = t & 31, w5 = t >> 5;
    const int gA = t >> 4;                      // 0..15 (j base) for A
    const int e4 = (t & 15) << 2;               // 0..60

    // A: register cache of this thread's 8 HD row-slices
    ulonglong2 hdc[8];
    if (t < 256) {
        #pragma unroll
        for (int jj = 0; jj < 8; jj++)
            hdc[jj] = *(const ulonglong2*)&S[SM_HD + (gA + (jj << 4)) * 64 + e4];
    }

    for (int i = -1; i < Nc; i++) {
        if (t < 256) {
            // refresh the HD row B rewrote in iter i-1 (row i-1)
            int rrow = i - 1;
            if (rrow >= 0 && (rrow & 15) == gA)
                hdc[rrow >> 4] = *(const ulonglong2*)&S[SM_HD + rrow * 64 + e4];
            int rv_pref = 0;
            bool do_pref = (t < 128) && (i + 2 < Nc);
            if (do_pref) rv_pref = relrow[(i + 2) * Nc + t];
            if (i < Nc - 1) {
                const int s = i + 1;
                const int* rv = rvs + (s % 3) * 128;
                float a0 = -1e30f, a1 = -1e30f, a2 = -1e30f, a3 = -1e30f;
                #pragma unroll
                for (int jj = 0; jj < 8; jj++) {
                    int j = gA + (jj << 4);
                    int rvj = rv[j];
                    float d = S[SM_DISC + j];
                    ull d2 = packf2(d, d);
                    ulonglong2 rp = *(const ulonglong2*)&S[SM_RP + rvj * 64 + e4];
                    float2 u0 = unpackf2(f2fma(rp.x, d2, hdc[jj].x));
                    float2 u1 = unpackf2(f2fma(rp.y, d2, hdc[jj].y));
                    a0 = fmaxf(a0, u0.x); a1 = fmaxf(a1, u0.y);
                    a2 = fmaxf(a2, u1.x); a3 = fmaxf(a3, u1.y);
                }
                a0 = fmaxf(a0, __shfl_xor_sync(0xffffffffu, a0, 16));
                a1 = fmaxf(a1, __shfl_xor_sync(0xffffffffu, a1, 16));
                a2 = fmaxf(a2, __shfl_xor_sync(0xffffffffu, a2, 16));
                a3 = fmaxf(a3, __shfl_xor_sync(0xffffffffu, a3, 16));
                if (lane < 16)
                    *(float4*)&S[SM_PBUF + (s & 1) * 576 + w5 * 64 + e4] =
                        make_float4(a0, a1, a2, a3);
            }
            if (do_pref) {
                int val = (t < len) ? rv_pref : 0;
                int ring2 = (i + 2) % 3;
                if (t == i + 1) { corrv[ring2] = val; val = 0; }  // excluded -> side
                rvs[ring2 * 128 + t] = val;
            }
        } else if (i >= 0) {
            const int u = t - 256;               // 0..127
            const int e = u >> 1, half = u & 1;
            // P0: 9-way max -> clamp -> dis_pre
            if (u < 64) {
                float m = S[SM_PBUF + (i & 1) * 576 + u];
                #pragma unroll
                for (int s2 = 1; s2 < 9; s2++)
                    m = fmaxf(m, S[SM_PBUF + (i & 1) * 576 + s2 * 64 + u]);
                S[SM_DP + u] = (m < -5e28f) ? 0.f : fminf(m, 0.f);
            }
            BAR_B();
            // P1: r AND z fused (2 thr/output, packed weights in regs)
            {
                const ulonglong2* dp2 = (const ulonglong2*)&S[SM_DP + half * 32];
                ull ra = 0, rb = 0, za = 0, zb = 0;
                #pragma unroll
                for (int c = 0; c < 8; c++) {
                    ulonglong2 d = dp2[c];
                    ra = f2fma(wR2[2 * c], d.x, ra);
                    rb = f2fma(wR2[2 * c + 1], d.y, rb);
                    za = f2fma(wZ2[2 * c], d.x, za);
                    zb = f2fma(wZ2[2 * c + 1], d.y, zb);
                }
                float2 pra = unpackf2(ra), prb = unpackf2(rb);
                float2 pza = unpackf2(za), pzb = unpackf2(zb);
                float rs = (pra.x + pra.y) + (prb.x + prb.y);
                float zs = (pza.x + pza.y) + (pzb.x + pzb.y);
                rs += __shfl_xor_sync(0xffffffffu, rs, 1);
                zs += __shfl_xor_sync(0xffffffffu, zs, 1);
                if (half == 0) {
                    float vr = S[SM_NP + i * 192 + e] + rs;
                    float vz = S[SM_NP + i * 192 + 64 + e] + zs;
                    float r = 1.0f / (1.0f + __expf(-vr));
                    S[SM_RD + e] = r * S[SM_DP + e];
                    S[SM_Z + e] = 1.0f / (1.0f + __expf(-vz));
                }
            }
            BAR_B();
            // P2: h_hat on (r*dp) + fused GRU update (packed)
            {
                const ulonglong2* rd2 = (const ulonglong2*)&S[SM_RD + half * 32];
                ull ta = 0, tb = 0;
                #pragma unroll
                for (int c = 0; c < 8; c++) {
                    ulonglong2 d = rd2[c];
                    ta = f2fma(wT2[2 * c], d.x, ta);
                    tb = f2fma(wT2[2 * c + 1], d.y, tb);
                }
                float2 pta = unpackf2(ta), ptb = unpackf2(tb);
                float sum = (pta.x + pta.y) + (ptb.x + ptb.y);
                sum += __shfl_xor_sync(0xffffffffu, sum, 1);
                if (half == 0) {
                    float v = S[SM_NP + i * 192 + 128 + e] + sum;
                    float ex = __expf(2.f * v);
                    float hh = 1.f - 2.f / (ex + 1.f);   // tanh, overflow-safe
                    float z = S[SM_Z + e], dp = S[SM_DP + e];
                    float up = (1.0f - z) * dp + z * hh;
                    float nr = (i < len) ? up : S[SM_HID + i * 64 + e];
                    S[SM_HID + i * 64 + e] = nr;
                    S[SM_NR + e] = nr;
                }
            }
            BAR_B();
            // P3: HD row refresh + fused correction term for step i+1 (packed)
            {
                const ulonglong2* n2 = (const ulonglong2*)&S[SM_NR + half * 32];
                ull ha = 0, hb = 0;
                #pragma unroll
                for (int c = 0; c < 8; c++) {
                    ulonglong2 n = n2[c];
                    ha = f2fma(wH2[2 * c], n.x, ha);
                    hb = f2fma(wH2[2 * c + 1], n.y, hb);
                }
                float2 pha = unpackf2(ha), phb = unpackf2(hb);
                float sum = (pha.x + pha.y) + (phb.x + phb.y);
                sum += __shfl_xor_sync(0xffffffffu, sum, 1);
                if (half == 0) {
                    float di = S[SM_DISC + i];
                    float hd = (S[SM_BIN + e] + sum) * di;
                    S[SM_HD + i * 64 + e] = hd;
                    if (i + 1 < Nc) {
                        int v = corrv[(i + 1) % 3];
                        float c = -1e30f;
                        if (v != 0) c = fmaf(S[SM_RP + v * 64 + e], di, hd);
                        S[SM_PBUF + ((i + 1) & 1) * 576 + 512 + e] = c;
                    }
                }
            }
        }
        __syncthreads();
    }

    // ---------------- final head ----------------
    for (int x = t; x < 512; x += NTHR) {
        int tE = x & 63, tJG = x >> 6;
        float acc = -1e30f;
        #pragma unroll
        for (int jj = 0; jj < 16; jj++) {
            int j = tJG + (jj << 3);
            if (j < len) acc = fmaxf(acc, S[SM_HID + j * 64 + tE]);
        }
        S[SM_PBUF + tJG * 64 + tE] = acc;
    }
    __syncthreads();
    if (t < 64) {
        float m = S[SM_PBUF + t];
        #pragma unroll
        for (int g = 1; g < 8; g++) m = fmaxf(m, S[SM_PBUF + g * 64 + t]);
        S[SM_FIN + 128 + t] = m;                               // sub
        S[SM_FIN + t]       = S[SM_HID + t];                   // user
        S[SM_FIN + 64 + t]  = S[SM_HID + (len - 1) * 64 + t];  // item
    }
    __syncthreads();
    if (t < 128) {  // ua / ia
        int which = t >> 6, e = t & 63;
        const float* first = which ? &S[SM_FIN + 64] : &S[SM_FIN];
        float acc = p.b_co[e];
        #pragma unroll 4
        for (int k = 0; k < 64; k++) acc += first[k] * p.W_co[k * 64 + e];
        #pragma unroll 4
        for (int k = 0; k < 64; k++) acc += S[SM_FIN + 128 + k] * p.W_co[(64 + k) * 64 + e];
        S[SM_FIN + 192 + which * 64 + e] = fmaxf(acc, 0.f);
    }
    __syncthreads();
    if (t < 192) {  // temp = [ua*user, sub, ia*item]
        float v;
        if (t < 64)       v = S[SM_FIN + 192 + t] * S[SM_FIN + t];
        else if (t < 128) v = S[SM_FIN + 128 + (t - 64)];
        else              v = S[SM_FIN + 256 + (t - 128)] * S[SM_FIN + 64 + (t - 128)];
        S[SM_FIN + 320 + t] = v;
    }
    __syncthreads();
    if (t < 128) {
        float acc = p.b1[t];
        #pragma unroll 4
        for (int k = 0; k < 192; k++) acc += S[SM_FIN + 320 + k] * p.W1[k * 128 + t];
        S[SM_FIN + 512 + t] = fmaxf(acc, 0.f);
    }
    __syncthreads();
    if (t < 64) {
        float acc = p.b2[t];
        #pragma unroll 4
        for (int k = 0; k < 128; k++) acc += S[SM_FIN + 512 + k] * p.W2[k * 64 + t];
        S[SM_FIN + 640 + t] = fmaxf(acc, 0.f);
    }
    __syncthreads();
    if (t < 32) {
        float acc = p.b3[t];
        #pragma unroll 4
        for (int k = 0; k < 64; k++) acc += S[SM_FIN + 640 + k] * p.W3[k * 32 + t];
        S[SM_FIN + 704 + t] = fmaxf(acc, 0.f);
    }
    __syncthreads();
    if (t == 0) {
        float acc = p.b4[0];
        #pragma unroll
        for (int k = 0; k < 32; k++) acc += S[SM_FIN + 704 + k] * p.W4[k];
        p.out[b] = 1.0f / (1.0f + __expf(-acc));
    }
}

// ---------------------------------------------------------------------------
extern "C" void kernel_launch(void* const* d_in, const int* in_sizes, int n_in,
                              void* d_out, int out_size) {
    GParams p;
    p.node_slice   = (const int*)d_in[0];
    p.type_slice   = (const int*)d_in[1];
    p.distance     = (const float*)d_in[2];
    p.rel_matrix   = (const int*)d_in[3];
    p.input_length = (const int*)d_in[4];
    int o = (n_in >= 27) ? 6 : 5;
    p.emb_table  = (const float*)d_in[o + 0];
    p.type_table = (const float*)d_in[o + 1];
    p.rel_table  = (const float*)d_in[o + 2];
    p.W_in = (const float*)d_in[o + 3];  p.b_in = (const float*)d_in[o + 4];
    p.Wr   = (const float*)d_in[o + 5];  p.br   = (const float*)d_in[o + 6];
    p.Wz   = (const float*)d_in[o + 7];  p.bz   = (const float*)d_in[o + 8];
    p.Wt   = (const float*)d_in[o + 9];  p.bt   = (const float*)d_in[o + 10];
    p.W_co = (const float*)d_in[o + 11]; p.b_co = (const float*)d_in[o + 12];
    p.W1   = (const float*)d_in[o + 13]; p.b1   = (const float*)d_in[o + 14];
    p.W2   = (const float*)d_in[o + 15]; p.b2   = (const float*)d_in[o + 16];
    p.W3   = (const float*)d_in[o + 17]; p.b3   = (const float*)d_in[o + 18];
    p.W4   = (const float*)d_in[o + 19]; p.b4   = (const float*)d_in[o + 20];
    p.out  = (float*)d_out;

    cudaFuncSetAttribute(ggnn_main, cudaFuncAttributeMaxDynamicSharedMemorySize,
                         SMEM_FLOATS * (int)sizeof(float));

    ggnn_pre<<<TYPEC + 1, 192>>>(p);
    ggnn_main<<<Bc, NTHR, SMEM_FLOATS * (int)sizeof(float)>>>(p);
}

// round 14
// speedup vs baseline: 1.1247x; 1.1247x over previous
#include <cuda_runtime.h>
#include <cuda_bf16.h>
#include <math.h>

// Problem constants
#define Bc 128
#define Nc 128
#define Ec 64
#define TYPEC 201   // TYPE_NUM+1
#define RELC  51    // REL_NUM+1

#define NTHR 384
#define BAR_B() asm volatile("bar.sync 1, 128;" ::: "memory")

typedef unsigned long long ull;

// ---- Blackwell packed f32x2 helpers (fma/pack/unpack only) ----
__device__ __forceinline__ ull f2fma(ull a, ull b, ull c) {
    ull d; asm("fma.rn.f32x2 %0, %1, %2, %3;" : "=l"(d) : "l"(a), "l"(b), "l"(c)); return d;
}
__device__ __forceinline__ ull packf2(float lo, float hi) {
    ull d; asm("mov.b64 %0, {%1, %2};" : "=l"(d) : "f"(lo), "f"(hi)); return d;
}
__device__ __forceinline__ float2 unpackf2(ull v) {
    float lo, hi; asm("mov.b64 {%0, %1}, %2;" : "=f"(lo), "=f"(hi) : "l"(v));
    return make_float2(lo, hi);
}

// Precomputed batch-independent tables
__device__ float g_typeproj[TYPEC * 192];
__device__ float g_relproj[RELC * 64];

struct GParams {
    const int*   node_slice;
    const int*   type_slice;
    const float* distance;
    const int*   rel_matrix;
    const int*   input_length;
    const float* emb_table;
    const float* type_table;
    const float* rel_table;
    const float* W_in; const float* b_in;
    const float* Wr;   const float* br;
    const float* Wz;   const float* bz;
    const float* Wt;   const float* bt;
    const float* W_co; const float* b_co;
    const float* W1;   const float* b1;
    const float* W2;   const float* b2;
    const float* W3;   const float* b3;
    const float* W4;   const float* b4;
    float* out;
};

// ---------------------------------------------------------------------------
__global__ void ggnn_pre(GParams p) {
    int blk = blockIdx.x;
    int t = threadIdx.x;
    if (blk < TYPEC) {
        if (t < 192) {
            int gate = t >> 6, e = t & 63;
            const float* Wg = (gate == 0) ? p.Wr : ((gate == 1) ? p.Wz : p.Wt);
            const float* bg = (gate == 0) ? p.br : ((gate == 1) ? p.bz : p.bt);
            float acc = bg[e];
            #pragma unroll
            for (int k = 0; k < 32; k++)
                acc += p.type_table[blk * 32 + k] * Wg[k * 64 + e];
            g_typeproj[blk * 192 + t] = acc;
        }
    } else {
        if (t < 64) {
            for (int v = 0; v < RELC; v++) {
                float acc = 0.f;
                #pragma unroll
                for (int k = 0; k < 32; k++)
                    acc += p.rel_table[v * 32 + k] * p.W_in[(64 + k) * 64 + t];
                g_relproj[v * 64 + t] = acc;
            }
        }
    }
}

// ---------------------------------------------------------------------------
// Shared layout (float offsets) — identical to R10
// ---------------------------------------------------------------------------
#define SM_HD    0        // 8192 : (hidden@W_h + b_in) * disc[row]
#define SM_HID   8192     // 8192 : raw hidden state
#define SM_NP    16384    // 24576
#define SM_RP    40960    // 3264 (row 0 = +1e30 sentinel), pad to 3328
#define SM_DISC  44288    // 128
#define SM_PBUF  44416    // 2 * 9 * 64 = 1152 (8 A slots + 1 corr slot)
#define SM_DP    45568    // 64
#define SM_RD    45632    // 64 : r * dis_pre
#define SM_Z     45696    // 64 : z gate scratch
#define SM_NR    45760    // 64
#define SM_BIN   45824    // 64
#define SM_RV    45888    // 3*128 ints : rel row ring
#define SM_TV    46272    // 128 ints
#define SM_CORRV 46400    // 3 ints (pad 64)
#define SM_FIN   46464    // 768
#define SM_STAGE 47232    // 8192 (init GEMM staging)
#define SMEM_FLOATS 55424

__global__ void __launch_bounds__(NTHR, 1) ggnn_main(GParams p) {
    extern __shared__ float S[];
    const int t = threadIdx.x;
    const int b = blockIdx.x;
    int* rvs = (int*)&S[SM_RV];
    int* tvs = (int*)&S[SM_TV];
    int* corrv = (int*)&S[SM_CORRV];
    const int len = p.input_length[b];
    const int* relrow = p.rel_matrix + (long long)b * Nc * Nc;

    // ---------------- init gathers ----------------
    {
        const float4* emb4 = (const float4*)p.emb_table;
        float4* hid4 = (float4*)&S[SM_HID];
        for (int idx = t; idx < Nc * 16; idx += NTHR) {
            int j = idx >> 4, q = idx & 15;
            long long nd = p.node_slice[b * Nc + j];
            hid4[idx] = emb4[nd * 16 + q];
        }
    }
    if (t < 128) {
        S[SM_DISC + t] = -0.1f * p.distance[b * Nc + t];
        tvs[t] = p.type_slice[b * Nc + t];
        rvs[t] = (t < len) ? relrow[t] : 0;      // ring slot 0, len-masked
    }
    for (int idx = t; idx < RELC * 64; idx += NTHR) S[SM_RP + idx] = g_relproj[idx];
    if (t < 64) {
        S[SM_RP + t] = 1e30f;                    // sentinel row: rv==0 -> s ~ -1e29
        S[SM_BIN + t] = p.b_in[t];
        S[SM_PBUF + 512 + t] = -1e30f;           // corr slot of buffer 0
    }

    // ---- persistent PACKED gate weights in registers (group B: t>=256) ----
    ull wR2[16], wZ2[16], wT2[16], wH2[16];
    if (t >= 256) {
        int u = t - 256;
        int e = u >> 1, half = u & 1;
        int kb = 96 + half * 32;
        #pragma unroll
        for (int q = 0; q < 16; q++) {
            wR2[q] = packf2(p.Wr[(kb + 2 * q) * 64 + e], p.Wr[(kb + 2 * q + 1) * 64 + e]);
            wZ2[q] = packf2(p.Wz[(kb + 2 * q) * 64 + e], p.Wz[(kb + 2 * q + 1) * 64 + e]);
            wT2[q] = packf2(p.Wt[(kb + 2 * q) * 64 + e], p.Wt[(kb + 2 * q + 1) * 64 + e]);
            wH2[q] = packf2(p.W_in[(half * 32 + 2 * q) * 64 + e],
                            p.W_in[(half * 32 + 2 * q + 1) * 64 + e]);
        }
    }
    __syncthreads();

    // ---------------- HD init: HD = (hidden @ W_h + b_in) * disc ----------------
    for (int idx = t; idx < 4096; idx += NTHR) S[SM_STAGE + idx] = p.W_in[idx];
    __syncthreads();
    for (int x = t; x < 512; x += NTHR) {
        int j0 = (x >> 4) << 2, e0 = (x & 15) << 2;
        float acc[4][4];
        #pragma unroll
        for (int m = 0; m < 4; m++)
            #pragma unroll
            for (int n = 0; n < 4; n++) acc[m][n] = S[SM_BIN + e0 + n];
        #pragma unroll 4
        for (int k = 0; k < 64; k++) {
            float4 w = *(const float4*)&S[SM_STAGE + k * 64 + e0];
            #pragma unroll
            for (int m = 0; m < 4; m++) {
                float h = S[SM_HID + (j0 + m) * 64 + k];
                acc[m][0] += h * w.x; acc[m][1] += h * w.y;
                acc[m][2] += h * w.z; acc[m][3] += h * w.w;
            }
        }
        #pragma unroll
        for (int m = 0; m < 4; m++) {
            float d = S[SM_DISC + j0 + m];
            #pragma unroll
            for (int n = 0; n < 4; n++)
                S[SM_HD + (j0 + m) * 64 + e0 + n] = acc[m][n] * d;
        }
    }
    __syncthreads();

    // -------- now_part: typeproj[tv] + node_emb @ Wg[32:96] --------
    for (int idx = t; idx < 8192; idx += NTHR) {
        int k = idx >> 7, c = idx & 127;
        S[SM_STAGE + idx] = (c < 64) ? p.Wr[(32 + k) * 64 + c]
                                     : p.Wz[(32 + k) * 64 + (c - 64)];
    }
    __syncthreads();
    for (int x = t; x < 1024; x += NTHR) {
        int i0 = (x >> 5) << 2, c0 = (x & 31) << 2;
        float acc[4][4];
        #pragma unroll
        for (int m = 0; m < 4; m++) {
            const float* tp = &g_typeproj[tvs[i0 + m] * 192 + c0];
            acc[m][0] = tp[0]; acc[m][1] = tp[1]; acc[m][2] = tp[2]; acc[m][3] = tp[3];
        }
        #pragma unroll 4
        for (int k = 0; k < 64; k++) {
            float4 w = *(const float4*)&S[SM_STAGE + k * 128 + c0];
            #pragma unroll
            for (int m = 0; m < 4; m++) {
                float h = S[SM_HID + (i0 + m) * 64 + k];
                acc[m][0] += h * w.x; acc[m][1] += h * w.y;
                acc[m][2] += h * w.z; acc[m][3] += h * w.w;
            }
        }
        #pragma unroll
        for (int m = 0; m < 4; m++)
            #pragma unroll
            for (int n = 0; n < 4; n++)
                S[SM_NP + (i0 + m) * 192 + c0 + n] = acc[m][n];
    }
    __syncthreads();
    for (int idx = t; idx < 4096; idx += NTHR) {
        int k = idx >> 6, e = idx & 63;
        S[SM_STAGE + idx] = p.Wt[(32 + k) * 64 + e];
    }
    __syncthreads();
    for (int x = t; x < 512; x += NTHR) {
        int i0 = (x >> 4) << 2, e0 = (x & 15) << 2;
        float acc[4][4];
        #pragma unroll
        for (int m = 0; m < 4; m++) {
            const float* tp = &g_typeproj[tvs[i0 + m] * 192 + 128 + e0];
            acc[m][0] = tp[0]; acc[m][1] = tp[1]; acc[m][2] = tp[2]; acc[m][3] = tp[3];
        }
        #pragma unroll 4
        for (int k = 0; k < 64; k++) {
            float4 w = *(const float4*)&S[SM_STAGE + k * 64 + e0];
            #pragma unroll
            for (int m = 0; m < 4; m++) {
                float h = S[SM_HID + (i0 + m) * 64 + k];
                acc[m][0] += h * w.x; acc[m][1] += h * w.y;
                acc[m][2] += h * w.z; acc[m][3] += h * w.w;
            }
        }
        #pragma unroll
        for (int m = 0; m < 4; m++)
            #pragma unroll
            for (int n = 0; n < 4; n++)
                S[SM_NP + (i0 + m) * 192 + 128 + e0 + n] = acc[m][n];
    }
    __syncthreads();

    // ---------------- pipelined scan ----------------
    // iter i: A (t<256, 8 warps; 16 groups of 16 threads, group g scans the 8
    // CONTIGUOUS rows j in [8g, 8g+8)) computes max_j f32x2-fma(rp, d, hd)
    // partials for step i+1 — all 8 rvj and discounts vector-loaded up front so
    // the 8 rp/hd load pairs pipeline; B (t>=256, 4 warps): 9-max+clamp ->
    // r,z -> hhat+update -> HD+corr.
    const int lane = t & 31, w5 = t >> 5;
    const int gA = t >> 4;                      // 0..15 (group) for A
    const int jb = gA << 3;                     // base j = 8*gA (contiguous)
    const int e4 = (lane & 15) << 2;            // 0..60
    for (int i = -1; i < Nc; i++) {
        if (t < 256) {
            int rv_pref = 0;
            bool do_pref = (t < 128) && (i + 2 < Nc);
            if (do_pref) rv_pref = relrow[(i + 2) * Nc + t];
            if (i < Nc - 1) {
                const int s = i + 1;
                const int* rv = rvs + (s % 3) * 128 + jb;
                int4 rva = *(const int4*)rv;
                int4 rvb = *(const int4*)(rv + 4);
                float4 da = *(const float4*)&S[SM_DISC + jb];
                float4 db = *(const float4*)&S[SM_DISC + jb + 4];
                int rvj[8] = {rva.x, rva.y, rva.z, rva.w, rvb.x, rvb.y, rvb.z, rvb.w};
                float dj[8] = {da.x, da.y, da.z, da.w, db.x, db.y, db.z, db.w};
                float a0 = -1e30f, a1 = -1e30f, a2 = -1e30f, a3 = -1e30f;
                #pragma unroll
                for (int jj = 0; jj < 8; jj++) {
                    int j = jb + jj;
                    ull d2 = packf2(dj[jj], dj[jj]);
                    ulonglong2 hd = *(const ulonglong2*)&S[SM_HD + j * 64 + e4];
                    ulonglong2 rp = *(const ulonglong2*)&S[SM_RP + rvj[jj] * 64 + e4];
                    float2 u0 = unpackf2(f2fma(rp.x, d2, hd.x));
                    float2 u1 = unpackf2(f2fma(rp.y, d2, hd.y));
                    a0 = fmaxf(a0, u0.x); a1 = fmaxf(a1, u0.y);
                    a2 = fmaxf(a2, u1.x); a3 = fmaxf(a3, u1.y);
                }
                a0 = fmaxf(a0, __shfl_xor_sync(0xffffffffu, a0, 16));
                a1 = fmaxf(a1, __shfl_xor_sync(0xffffffffu, a1, 16));
                a2 = fmaxf(a2, __shfl_xor_sync(0xffffffffu, a2, 16));
                a3 = fmaxf(a3, __shfl_xor_sync(0xffffffffu, a3, 16));
                if (lane < 16)
                    *(float4*)&S[SM_PBUF + (s & 1) * 576 + w5 * 64 + e4] =
                        make_float4(a0, a1, a2, a3);
            }
            if (do_pref) {
                int val = (t < len) ? rv_pref : 0;
                int ring2 = (i + 2) % 3;
                if (t == i + 1) { corrv[ring2] = val; val = 0; }  // excluded -> side
                rvs[ring2 * 128 + t] = val;
            }
        } else if (i >= 0) {
            const int u = t - 256;               // 0..127
            const int e = u >> 1, half = u & 1;
            // P0: 9-way max -> clamp -> dis_pre
            if (u < 64) {
                float m = S[SM_PBUF + (i & 1) * 576 + u];
                #pragma unroll
                for (int s2 = 1; s2 < 9; s2++)
                    m = fmaxf(m, S[SM_PBUF + (i & 1) * 576 + s2 * 64 + u]);
                S[SM_DP + u] = (m < -5e28f) ? 0.f : fminf(m, 0.f);
            }
            BAR_B();
            // P1: r AND z fused (2 thr/output, packed weights in regs)
            {
                const ulonglong2* dp2 = (const ulonglong2*)&S[SM_DP + half * 32];
                ull ra = 0, rb = 0, za = 0, zb = 0;
                #pragma unroll
                for (int c = 0; c < 8; c++) {
                    ulonglong2 d = dp2[c];
                    ra = f2fma(wR2[2 * c], d.x, ra);
                    rb = f2fma(wR2[2 * c + 1], d.y, rb);
                    za = f2fma(wZ2[2 * c], d.x, za);
                    zb = f2fma(wZ2[2 * c + 1], d.y, zb);
                }
                float2 pra = unpackf2(ra), prb = unpackf2(rb);
                float2 pza = unpackf2(za), pzb = unpackf2(zb);
                float rs = (pra.x + pra.y) + (prb.x + prb.y);
                float zs = (pza.x + pza.y) + (pzb.x + pzb.y);
                rs += __shfl_xor_sync(0xffffffffu, rs, 1);
                zs += __shfl_xor_sync(0xffffffffu, zs, 1);
                if (half == 0) {
                    float vr = S[SM_NP + i * 192 + e] + rs;
                    float vz = S[SM_NP + i * 192 + 64 + e] + zs;
                    float r = 1.0f / (1.0f + __expf(-vr));
                    S[SM_RD + e] = r * S[SM_DP + e];
                    S[SM_Z + e] = 1.0f / (1.0f + __expf(-vz));
                }
            }
            BAR_B();
            // P2: h_hat on (r*dp) + fused GRU update (packed)
            {
                const ulonglong2* rd2 = (const ulonglong2*)&S[SM_RD + half * 32];
                ull ta = 0, tb = 0;
                #pragma unroll
                for (int c = 0; c < 8; c++) {
                    ulonglong2 d = rd2[c];
                    ta = f2fma(wT2[2 * c], d.x, ta);
                    tb = f2fma(wT2[2 * c + 1], d.y, tb);
                }
                float2 pta = unpackf2(ta), ptb = unpackf2(tb);
                float sum = (pta.x + pta.y) + (ptb.x + ptb.y);
                sum += __shfl_xor_sync(0xffffffffu, sum, 1);
                if (half == 0) {
                    float v = S[SM_NP + i * 192 + 128 + e] + sum;
                    float ex = __expf(2.f * v);
                    float hh = 1.f - 2.f / (ex + 1.f);   // tanh, overflow-safe
                    float z = S[SM_Z + e], dp = S[SM_DP + e];
                    float up = (1.0f - z) * dp + z * hh;
                    float nr = (i < len) ? up : S[SM_HID + i * 64 + e];
                    S[SM_HID + i * 64 + e] = nr;
                    S[SM_NR + e] = nr;
                }
            }
            BAR_B();
            // P3: HD row refresh + fused correction term for step i+1 (packed)
            {
                const ulonglong2* n2 = (const ulonglong2*)&S[SM_NR + half * 32];
                ull ha = 0, hb = 0;
                #pragma unroll
                for (int c = 0; c < 8; c++) {
                    ulonglong2 n = n2[c];
                    ha = f2fma(wH2[2 * c], n.x, ha);
                    hb = f2fma(wH2[2 * c + 1], n.y, hb);
                }
                float2 pha = unpackf2(ha), phb = unpackf2(hb);
                float sum = (pha.x + pha.y) + (phb.x + phb.y);
                sum += __shfl_xor_sync(0xffffffffu, sum, 1);
                if (half == 0) {
                    float di = S[SM_DISC + i];
                    float hd = (S[SM_BIN + e] + sum) * di;
                    S[SM_HD + i * 64 + e] = hd;
                    if (i + 1 < Nc) {
                        int v = corrv[(i + 1) % 3];
                        float c = -1e30f;
                        if (v != 0) c = fmaf(S[SM_RP + v * 64 + e], di, hd);
                        S[SM_PBUF + ((i + 1) & 1) * 576 + 512 + e] = c;
                    }
                }
            }
        }
        __syncthreads();
    }

    // ---------------- final head ----------------
    for (int x = t; x < 512; x += NTHR) {
        int tE = x & 63, tJG = x >> 6;
        float acc = -1e30f;
        #pragma unroll
        for (int jj = 0; jj < 16; jj++) {
            int j = tJG + (jj << 3);
            if (j < len) acc = fmaxf(acc, S[SM_HID + j * 64 + tE]);
        }
        S[SM_PBUF + tJG * 64 + tE] = acc;
    }
    __syncthreads();
    if (t < 64) {
        float m = S[SM_PBUF + t];
        #pragma unroll
        for (int g = 1; g < 8; g++) m = fmaxf(m, S[SM_PBUF + g * 64 + t]);
        S[SM_FIN + 128 + t] = m;                               // sub
        S[SM_FIN + t]       = S[SM_HID + t];                   // user
        S[SM_FIN + 64 + t]  = S[SM_HID + (len - 1) * 64 + t];  // item
    }
    __syncthreads();
    if (t < 128) {  // ua / ia
        int which = t >> 6, e = t & 63;
        const float* first = which ? &S[SM_FIN + 64] : &S[SM_FIN];
        float acc = p.b_co[e];
        #pragma unroll 4
        for (int k = 0; k < 64; k++) acc += first[k] * p.W_co[k * 64 + e];
        #pragma unroll 4
        for (int k = 0; k < 64; k++) acc += S[SM_FIN + 128 + k] * p.W_co[(64 + k) * 64 + e];
        S[SM_FIN + 192 + which * 64 + e] = fmaxf(acc, 0.f);
    }
    __syncthreads();
    if (t < 192) {  // temp = [ua*user, sub, ia*item]
        float v;
        if (t < 64)       v = S[SM_FIN + 192 + t] * S[SM_FIN + t];
        else if (t < 128) v = S[SM_FIN + 128 + (t - 64)];
        else              v = S[SM_FIN + 256 + (t - 128)] * S[SM_FIN + 64 + (t - 128)];
        S[SM_FIN + 320 + t] = v;
    }
    __syncthreads();
    if (t < 128) {
        float acc = p.b1[t];
        #pragma unroll 4
        for (int k = 0; k < 192; k++) acc += S[SM_FIN + 320 + k] * p.W1[k * 128 + t];
        S[SM_FIN + 512 + t] = fmaxf(acc, 0.f);
    }
    __syncthreads();
    if (t < 64) {
        float acc = p.b2[t];
        #pragma unroll 4
        for (int k = 0; k < 128; k++) acc += S[SM_FIN + 512 + k] * p.W2[k * 64 + t];
        S[SM_FIN + 640 + t] = fmaxf(acc, 0.f);
    }
    __syncthreads();
    if (t < 32) {
        float acc = p.b3[t];
        #pragma unroll 4
        for (int k = 0; k < 64; k++) acc += S[SM_FIN + 640 + k] * p.W3[k * 32 + t];
        S[SM_FIN + 704 + t] = fmaxf(acc, 0.f);
    }
    __syncthreads();
    if (t == 0) {
        float acc = p.b4[0];
        #pragma unroll
        for (int k = 0; k < 32; k++) acc += S[SM_FIN + 704 + k] * p.W4[k];
        p.out[b] = 1.0f / (1.0f + __expf(-acc));
    }
}

// ---------------------------------------------------------------------------
extern "C" void kernel_launch(void* const* d_in, const int* in_sizes, int n_in,
                              void* d_out, int out_size) {
    GParams p;
    p.node_slice   = (const int*)d_in[0];
    p.type_slice   = (const int*)d_in[1];
    p.distance     = (const float*)d_in[2];
    p.rel_matrix   = (const int*)d_in[3];
    p.input_length = (const int*)d_in[4];
    int o = (n_in >= 27) ? 6 : 5;
    p.emb_table  = (const float*)d_in[o + 0];
    p.type_table = (const float*)d_in[o + 1];
    p.rel_table  = (const float*)d_in[o + 2];
    p.W_in = (const float*)d_in[o + 3];  p.b_in = (const float*)d_in[o + 4];
    p.Wr   = (const float*)d_in[o + 5];  p.br   = (const float*)d_in[o + 6];
    p.Wz   = (const float*)d_in[o + 7];  p.bz   = (const float*)d_in[o + 8];
    p.Wt   = (const float*)d_in[o + 9];  p.bt   = (const float*)d_in[o + 10];
    p.W_co = (const float*)d_in[o + 11]; p.b_co = (const float*)d_in[o + 12];
    p.W1   = (const float*)d_in[o + 13]; p.b1   = (const float*)d_in[o + 14];
    p.W2   = (const float*)d_in[o + 15]; p.b2   = (const float*)d_in[o + 16];
    p.W3   = (const float*)d_in[o + 17]; p.b3   = (const float*)d_in[o + 18];
    p.W4   = (const float*)d_in[o + 19]; p.b4   = (const float*)d_in[o + 20];
    p.out  = (float*)d_out;

    cudaFuncSetAttribute(ggnn_main, cudaFuncAttributeMaxDynamicSharedMemorySize,
                         SMEM_FLOATS * (int)sizeof(float));

    ggnn_pre<<<TYPEC + 1, 192>>>(p);
    ggnn_main<<<Bc, NTHR, SMEM_FLOATS * (int)sizeof(float)>>>(p);
}

// round 15
// speedup vs baseline: 1.2254x; 1.0895x over previous
#include <cuda_runtime.h>
#include <cuda_bf16.h>
#include <math.h>

// Problem constants
#define Bc 128
#define Nc 128
#define Ec 64
#define TYPEC 201   // TYPE_NUM+1
#define RELC  51    // REL_NUM+1

#define NTHR 384
#define BAR_B() asm volatile("bar.sync 1, 128;" ::: "memory")

typedef unsigned long long ull;

// ---- Blackwell packed f32x2 helpers (fma/pack/unpack only) ----
__device__ __forceinline__ ull f2fma(ull a, ull b, ull c) {
    ull d; asm("fma.rn.f32x2 %0, %1, %2, %3;" : "=l"(d) : "l"(a), "l"(b), "l"(c)); return d;
}
__device__ __forceinline__ ull packf2(float lo, float hi) {
    ull d; asm("mov.b64 %0, {%1, %2};" : "=l"(d) : "f"(lo), "f"(hi)); return d;
}
__device__ __forceinline__ float2 unpackf2(ull v) {
    float lo, hi; asm("mov.b64 {%0, %1}, %2;" : "=f"(lo), "=f"(hi) : "l"(v));
    return make_float2(lo, hi);
}

// Precomputed batch-independent tables
__device__ float g_typeproj[TYPEC * 192];
__device__ float g_relproj[RELC * 64];

struct GParams {
    const int*   node_slice;
    const int*   type_slice;
    const float* distance;
    const int*   rel_matrix;
    const int*   input_length;
    const float* emb_table;
    const float* type_table;
    const float* rel_table;
    const float* W_in; const float* b_in;
    const float* Wr;   const float* br;
    const float* Wz;   const float* bz;
    const float* Wt;   const float* bt;
    const float* W_co; const float* b_co;
    const float* W1;   const float* b1;
    const float* W2;   const float* b2;
    const float* W3;   const float* b3;
    const float* W4;   const float* b4;
    float* out;
};

// ---------------------------------------------------------------------------
__global__ void ggnn_pre(GParams p) {
    int blk = blockIdx.x;
    int t = threadIdx.x;
    if (blk < TYPEC) {
        if (t < 192) {
            int gate = t >> 6, e = t & 63;
            const float* Wg = (gate == 0) ? p.Wr : ((gate == 1) ? p.Wz : p.Wt);
            const float* bg = (gate == 0) ? p.br : ((gate == 1) ? p.bz : p.bt);
            float acc = bg[e];
            #pragma unroll
            for (int k = 0; k < 32; k++)
                acc += p.type_table[blk * 32 + k] * Wg[k * 64 + e];
            g_typeproj[blk * 192 + t] = acc;
        }
    } else {
        if (t < 64) {
            for (int v = 0; v < RELC; v++) {
                float acc = 0.f;
                #pragma unroll
                for (int k = 0; k < 32; k++)
                    acc += p.rel_table[v * 32 + k] * p.W_in[(64 + k) * 64 + t];
                g_relproj[v * 64 + t] = acc;
            }
        }
    }
}

// ---------------------------------------------------------------------------
// Shared layout (float offsets) — identical to R10
// ---------------------------------------------------------------------------
#define SM_HD    0        // 8192 : (hidden@W_h + b_in) * disc[row]
#define SM_HID   8192     // 8192 : raw hidden state
#define SM_NP    16384    // 24576
#define SM_RP    40960    // 3264 (row 0 = +1e30 sentinel), pad to 3328
#define SM_DISC  44288    // 128
#define SM_PBUF  44416    // 2 * 9 * 64 = 1152 (8 A slots + 1 corr slot)
#define SM_DP    45568    // 64
#define SM_RD    45632    // 64 : r * dis_pre
#define SM_Z     45696    // 64 : z gate scratch
#define SM_NR    45760    // 64
#define SM_BIN   45824    // 64
#define SM_RV    45888    // 3*128 ints : rel row ring
#define SM_TV    46272    // 128 ints
#define SM_CORRV 46400    // 3 ints (pad 64)
#define SM_FIN   46464    // 768
#define SM_STAGE 47232    // 8192 (init GEMM staging)
#define SMEM_FLOATS 55424

__global__ void __launch_bounds__(NTHR, 1) ggnn_main(GParams p) {
    extern __shared__ float S[];
    const int t = threadIdx.x;
    const int b = blockIdx.x;
    int* rvs = (int*)&S[SM_RV];
    int* tvs = (int*)&S[SM_TV];
    int* corrv = (int*)&S[SM_CORRV];
    const int len = p.input_length[b];
    const int* relrow = p.rel_matrix + (long long)b * Nc * Nc;

    // ---------------- init gathers ----------------
    {
        const float4* emb4 = (const float4*)p.emb_table;
        float4* hid4 = (float4*)&S[SM_HID];
        for (int idx = t; idx < Nc * 16; idx += NTHR) {
            int j = idx >> 4, q = idx & 15;
            long long nd = p.node_slice[b * Nc + j];
            hid4[idx] = emb4[nd * 16 + q];
        }
    }
    if (t < 128) {
        S[SM_DISC + t] = -0.1f * p.distance[b * Nc + t];
        tvs[t] = p.type_slice[b * Nc + t];
        rvs[t] = (t < len) ? relrow[t] : 0;      // ring slot 0, len-masked
    }
    for (int idx = t; idx < RELC * 64; idx += NTHR) S[SM_RP + idx] = g_relproj[idx];
    if (t < 64) {
        S[SM_RP + t] = 1e30f;                    // sentinel row: rv==0 -> s ~ -1e29
        S[SM_BIN + t] = p.b_in[t];
        S[SM_PBUF + 512 + t] = -1e30f;           // corr slot of buffer 0
    }

    // ---- persistent PACKED gate weights in registers (group B, 128 regs) ----
    // wRZ2[32]: this thread's gate (r if half==0, z if half==1), FULL k-range.
    ull wRZ2[32], wT2[16], wH2[16];
    if (t >= 256) {
        int u = t - 256;
        int e = u >> 1, half = u & 1;
        const float* Wg = half ? p.Wz : p.Wr;
        #pragma unroll
        for (int c = 0; c < 32; c++)
            wRZ2[c] = packf2(Wg[(96 + 2 * c) * 64 + e], Wg[(96 + 2 * c + 1) * 64 + e]);
        int kb = 96 + half * 32;
        #pragma unroll
        for (int q = 0; q < 16; q++) {
            wT2[q] = packf2(p.Wt[(kb + 2 * q) * 64 + e], p.Wt[(kb + 2 * q + 1) * 64 + e]);
            wH2[q] = packf2(p.W_in[(half * 32 + 2 * q) * 64 + e],
                            p.W_in[(half * 32 + 2 * q + 1) * 64 + e]);
        }
    }
    __syncthreads();

    // ---------------- HD init: HD = (hidden @ W_h + b_in) * disc ----------------
    for (int idx = t; idx < 4096; idx += NTHR) S[SM_STAGE + idx] = p.W_in[idx];
    __syncthreads();
    for (int x = t; x < 512; x += NTHR) {
        int j0 = (x >> 4) << 2, e0 = (x & 15) << 2;
        float acc[4][4];
        #pragma unroll
        for (int m = 0; m < 4; m++)
            #pragma unroll
            for (int n = 0; n < 4; n++) acc[m][n] = S[SM_BIN + e0 + n];
        #pragma unroll 4
        for (int k = 0; k < 64; k++) {
            float4 w = *(const float4*)&S[SM_STAGE + k * 64 + e0];
            #pragma unroll
            for (int m = 0; m < 4; m++) {
                float h = S[SM_HID + (j0 + m) * 64 + k];
                acc[m][0] += h * w.x; acc[m][1] += h * w.y;
                acc[m][2] += h * w.z; acc[m][3] += h * w.w;
            }
        }
        #pragma unroll
        for (int m = 0; m < 4; m++) {
            float d = S[SM_DISC + j0 + m];
            #pragma unroll
            for (int n = 0; n < 4; n++)
                S[SM_HD + (j0 + m) * 64 + e0 + n] = acc[m][n] * d;
        }
    }
    __syncthreads();

    // -------- now_part: typeproj[tv] + node_emb @ Wg[32:96] --------
    for (int idx = t; idx < 8192; idx += NTHR) {
        int k = idx >> 7, c = idx & 127;
        S[SM_STAGE + idx] = (c < 64) ? p.Wr[(32 + k) * 64 + c]
                                     : p.Wz[(32 + k) * 64 + (c - 64)];
    }
    __syncthreads();
    for (int x = t; x < 1024; x += NTHR) {
        int i0 = (x >> 5) << 2, c0 = (x & 31) << 2;
        float acc[4][4];
        #pragma unroll
        for (int m = 0; m < 4; m++) {
            const float* tp = &g_typeproj[tvs[i0 + m] * 192 + c0];
            acc[m][0] = tp[0]; acc[m][1] = tp[1]; acc[m][2] = tp[2]; acc[m][3] = tp[3];
        }
        #pragma unroll 4
        for (int k = 0; k < 64; k++) {
            float4 w = *(const float4*)&S[SM_STAGE + k * 128 + c0];
            #pragma unroll
            for (int m = 0; m < 4; m++) {
                float h = S[SM_HID + (i0 + m) * 64 + k];
                acc[m][0] += h * w.x; acc[m][1] += h * w.y;
                acc[m][2] += h * w.z; acc[m][3] += h * w.w;
            }
        }
        #pragma unroll
        for (int m = 0; m < 4; m++)
            #pragma unroll
            for (int n = 0; n < 4; n++)
                S[SM_NP + (i0 + m) * 192 + c0 + n] = acc[m][n];
    }
    __syncthreads();
    for (int idx = t; idx < 4096; idx += NTHR) {
        int k = idx >> 6, e = idx & 63;
        S[SM_STAGE + idx] = p.Wt[(32 + k) * 64 + e];
    }
    __syncthreads();
    for (int x = t; x < 512; x += NTHR) {
        int i0 = (x >> 4) << 2, e0 = (x & 15) << 2;
        float acc[4][4];
        #pragma unroll
        for (int m = 0; m < 4; m++) {
            const float* tp = &g_typeproj[tvs[i0 + m] * 192 + 128 + e0];
            acc[m][0] = tp[0]; acc[m][1] = tp[1]; acc[m][2] = tp[2]; acc[m][3] = tp[3];
        }
        #pragma unroll 4
        for (int k = 0; k < 64; k++) {
            float4 w = *(const float4*)&S[SM_STAGE + k * 64 + e0];
            #pragma unroll
            for (int m = 0; m < 4; m++) {
                float h = S[SM_HID + (i0 + m) * 64 + k];
                acc[m][0] += h * w.x; acc[m][1] += h * w.y;
                acc[m][2] += h * w.z; acc[m][3] += h * w.w;
            }
        }
        #pragma unroll
        for (int m = 0; m < 4; m++)
            #pragma unroll
            for (int n = 0; n < 4; n++)
                S[SM_NP + (i0 + m) * 192 + 128 + e0 + n] = acc[m][n];
    }
    __syncthreads();

    // ---------------- pipelined scan ----------------
    // iter i: A (t<256, 8 warps) computes max_j f32x2-fma(rp, d, hd) partials
    // for step i+1; B (t>=256, 4 warps): 9-max+clamp -> r|z (split by gate,
    // no shfl) -> hhat+update -> HD+corr.
    const int lane = t & 31, w5 = t >> 5;
    const int gA = t >> 4;                      // 0..15 (j base) for A
    const int e4 = (t & 15) << 2;               // 0..60
    for (int i = -1; i < Nc; i++) {
        if (t < 256) {
            int rv_pref = 0;
            bool do_pref = (t < 128) && (i + 2 < Nc);
            if (do_pref) rv_pref = relrow[(i + 2) * Nc + t];
            if (i < Nc - 1) {
                const int s = i + 1;
                const int* rv = rvs + (s % 3) * 128;
                float a0 = -1e30f, a1 = -1e30f, a2 = -1e30f, a3 = -1e30f;
                #pragma unroll
                for (int jj = 0; jj < 8; jj++) {
                    int j = gA + (jj << 4);
                    int rvj = rv[j];
                    float d = S[SM_DISC + j];
                    ull d2 = packf2(d, d);
                    ulonglong2 hd = *(const ulonglong2*)&S[SM_HD + j * 64 + e4];
                    ulonglong2 rp = *(const ulonglong2*)&S[SM_RP + rvj * 64 + e4];
                    float2 u0 = unpackf2(f2fma(rp.x, d2, hd.x));
                    float2 u1 = unpackf2(f2fma(rp.y, d2, hd.y));
                    a0 = fmaxf(a0, u0.x); a1 = fmaxf(a1, u0.y);
                    a2 = fmaxf(a2, u1.x); a3 = fmaxf(a3, u1.y);
                }
                a0 = fmaxf(a0, __shfl_xor_sync(0xffffffffu, a0, 16));
                a1 = fmaxf(a1, __shfl_xor_sync(0xffffffffu, a1, 16));
                a2 = fmaxf(a2, __shfl_xor_sync(0xffffffffu, a2, 16));
                a3 = fmaxf(a3, __shfl_xor_sync(0xffffffffu, a3, 16));
                if (lane < 16)
                    *(float4*)&S[SM_PBUF + (s & 1) * 576 + w5 * 64 + e4] =
                        make_float4(a0, a1, a2, a3);
            }
            if (do_pref) {
                int val = (t < len) ? rv_pref : 0;
                int ring2 = (i + 2) % 3;
                if (t == i + 1) { corrv[ring2] = val; val = 0; }  // excluded -> side
                rvs[ring2 * 128 + t] = val;
            }
        } else if (i >= 0) {
            const int u = t - 256;               // 0..127
            const int e = u >> 1, half = u & 1;
            // P0: 9-way max -> clamp -> dis_pre
            if (u < 64) {
                float m = S[SM_PBUF + (i & 1) * 576 + u];
                #pragma unroll
                for (int s2 = 1; s2 < 9; s2++)
                    m = fmaxf(m, S[SM_PBUF + (i & 1) * 576 + s2 * 64 + u]);
                S[SM_DP + u] = (m < -5e28f) ? 0.f : fminf(m, 0.f);
            }
            BAR_B();
            // P1: r (half==0) / z (half==1), full-k per thread, no shfl
            {
                float dp_e = S[SM_DP + e];                       // early
                float np = S[SM_NP + i * 192 + half * 64 + e];   // early
                const ulonglong2* dp2 = (const ulonglong2*)&S[SM_DP];
                ull a0 = 0, a1 = 0, a2 = 0, a3 = 0;
                #pragma unroll
                for (int c = 0; c < 8; c++) {
                    ulonglong2 dA = dp2[2 * c], dB = dp2[2 * c + 1];
                    a0 = f2fma(wRZ2[4 * c + 0], dA.x, a0);
                    a1 = f2fma(wRZ2[4 * c + 1], dA.y, a1);
                    a2 = f2fma(wRZ2[4 * c + 2], dB.x, a2);
                    a3 = f2fma(wRZ2[4 * c + 3], dB.y, a3);
                }
                float2 q0 = unpackf2(a0), q1 = unpackf2(a1);
                float2 q2 = unpackf2(a2), q3 = unpackf2(a3);
                float sum = ((q0.x + q0.y) + (q1.x + q1.y))
                          + ((q2.x + q2.y) + (q3.x + q3.y));
                float g = 1.0f / (1.0f + __expf(-(np + sum)));
                if (half == 0) S[SM_RD + e] = g * dp_e;
                else           S[SM_Z + e] = g;
            }
            BAR_B();
            // P2: h_hat on (r*dp) + fused GRU update (packed, 2 thr/output)
            {
                float np_t = 0.f, hid_old = 0.f, dp_e = 0.f, z_e = 0.f;
                if (half == 0) {                                  // early loads
                    np_t = S[SM_NP + i * 192 + 128 + e];
                    hid_old = S[SM_HID + i * 64 + e];
                    dp_e = S[SM_DP + e];
                    z_e = S[SM_Z + e];
                }
                const ulonglong2* rd2 = (const ulonglong2*)&S[SM_RD + half * 32];
                ull ta = 0, tb = 0;
                #pragma unroll
                for (int c = 0; c < 8; c++) {
                    ulonglong2 d = rd2[c];
                    ta = f2fma(wT2[2 * c], d.x, ta);
                    tb = f2fma(wT2[2 * c + 1], d.y, tb);
                }
                float2 pta = unpackf2(ta), ptb = unpackf2(tb);
                float sum = (pta.x + pta.y) + (ptb.x + ptb.y);
                sum += __shfl_xor_sync(0xffffffffu, sum, 1);
                if (half == 0) {
                    float v = np_t + sum;
                    float ex = __expf(2.f * v);
                    float hh = 1.f - 2.f / (ex + 1.f);   // tanh, overflow-safe
                    float up = (1.0f - z_e) * dp_e + z_e * hh;
                    float nr = (i < len) ? up : hid_old;
                    S[SM_HID + i * 64 + e] = nr;
                    S[SM_NR + e] = nr;
                }
            }
            BAR_B();
            // P3: HD row refresh + fused correction term for step i+1 (packed)
            {
                float di = S[SM_DISC + i];                        // early loads
                float bin_e = 0.f, rp_c = 0.f;
                int vcorr = 0;
                if (half == 0) {
                    bin_e = S[SM_BIN + e];
                    if (i + 1 < Nc) {
                        vcorr = corrv[(i + 1) % 3];
                        rp_c = S[SM_RP + vcorr * 64 + e];
                    }
                }
                const ulonglong2* n2 = (const ulonglong2*)&S[SM_NR + half * 32];
                ull ha = 0, hb = 0;
                #pragma unroll
                for (int c = 0; c < 8; c++) {
                    ulonglong2 n = n2[c];
                    ha = f2fma(wH2[2 * c], n.x, ha);
                    hb = f2fma(wH2[2 * c + 1], n.y, hb);
                }
                float2 pha = unpackf2(ha), phb = unpackf2(hb);
                float sum = (pha.x + pha.y) + (phb.x + phb.y);
                sum += __shfl_xor_sync(0xffffffffu, sum, 1);
                if (half == 0) {
                    float hd = (bin_e + sum) * di;
                    S[SM_HD + i * 64 + e] = hd;
                    if (i + 1 < Nc) {
                        float c = (vcorr != 0) ? fmaf(rp_c, di, hd) : -1e30f;
                        S[SM_PBUF + ((i + 1) & 1) * 576 + 512 + e] = c;
                    }
                }
            }
        }
        __syncthreads();
    }

    // ---------------- final head ----------------
    for (int x = t; x < 512; x += NTHR) {
        int tE = x & 63, tJG = x >> 6;
        float acc = -1e30f;
        #pragma unroll
        for (int jj = 0; jj < 16; jj++) {
            int j = tJG + (jj << 3);
            if (j < len) acc = fmaxf(acc, S[SM_HID + j * 64 + tE]);
        }
        S[SM_PBUF + tJG * 64 + tE] = acc;
    }
    __syncthreads();
    if (t < 64) {
        float m = S[SM_PBUF + t];
        #pragma unroll
        for (int g = 1; g < 8; g++) m = fmaxf(m, S[SM_PBUF + g * 64 + t]);
        S[SM_FIN + 128 + t] = m;                               // sub
        S[SM_FIN + t]       = S[SM_HID + t];                   // user
        S[SM_FIN + 64 + t]  = S[SM_HID + (len - 1) * 64 + t];  // item
    }
    __syncthreads();
    if (t < 128) {  // ua / ia
        int which = t >> 6, e = t & 63;
        const float* first = which ? &S[SM_FIN + 64] : &S[SM_FIN];
        float acc = p.b_co[e];
        #pragma unroll 4
        for (int k = 0; k < 64; k++) acc += first[k] * p.W_co[k * 64 + e];
        #pragma unroll 4
        for (int k = 0; k < 64; k++) acc += S[SM_FIN + 128 + k] * p.W_co[(64 + k) * 64 + e];
        S[SM_FIN + 192 + which * 64 + e] = fmaxf(acc, 0.f);
    }
    __syncthreads();
    if (t < 192) {  // temp = [ua*user, sub, ia*item]
        float v;
        if (t < 64)       v = S[SM_FIN + 192 + t] * S[SM_FIN + t];
        else if (t < 128) v = S[SM_FIN + 128 + (t - 64)];
        else              v = S[SM_FIN + 256 + (t - 128)] * S[SM_FIN + 64 + (t - 128)];
        S[SM_FIN + 320 + t] = v;
    }
    __syncthreads();
    if (t < 128) {
        float acc = p.b1[t];
        #pragma unroll 4
        for (int k = 0; k < 192; k++) acc += S[SM_FIN + 320 + k] * p.W1[k * 128 + t];
        S[SM_FIN + 512 + t] = fmaxf(acc, 0.f);
    }
    __syncthreads();
    if (t < 64) {
        float acc = p.b2[t];
        #pragma unroll 4
        for (int k = 0; k < 128; k++) acc += S[SM_FIN + 512 + k] * p.W2[k * 64 + t];
        S[SM_FIN + 640 + t] = fmaxf(acc, 0.f);
    }
    __syncthreads();
    if (t < 32) {
        float acc = p.b3[t];
        #pragma unroll 4
        for (int k = 0; k < 64; k++) acc += S[SM_FIN + 640 + k] * p.W3[k * 32 + t];
        S[SM_FIN + 704 + t] = fmaxf(acc, 0.f);
    }
    __syncthreads();
    if (t == 0) {
        float acc = p.b4[0];
        #pragma unroll
        for (int k = 0; k < 32; k++) acc += S[SM_FIN + 704 + k] * p.W4[k];
        p.out[b] = 1.0f / (1.0f + __expf(-acc));
    }
}

// ---------------------------------------------------------------------------
extern "C" void kernel_launch(void* const* d_in, const int* in_sizes, int n_in,
                              void* d_out, int out_size) {
    GParams p;
    p.node_slice   = (const int*)d_in[0];
    p.type_slice   = (const int*)d_in[1];
    p.distance     = (const float*)d_in[2];
    p.rel_matrix   = (const int*)d_in[3];
    p.input_length = (const int*)d_in[4];
    int o = (n_in >= 27) ? 6 : 5;
    p.emb_table  = (const float*)d_in[o + 0];
    p.type_table = (const float*)d_in[o + 1];
    p.rel_table  = (const float*)d_in[o + 2];
    p.W_in = (const float*)d_in[o + 3];  p.b_in = (const float*)d_in[o + 4];
    p.Wr   = (const float*)d_in[o + 5];  p.br   = (const float*)d_in[o + 6];
    p.Wz   = (const float*)d_in[o + 7];  p.bz   = (const float*)d_in[o + 8];
    p.Wt   = (const float*)d_in[o + 9];  p.bt   = (const float*)d_in[o + 10];
    p.W_co = (const float*)d_in[o + 11]; p.b_co = (const float*)d_in[o + 12];
    p.W1   = (const float*)d_in[o + 13]; p.b1   = (const float*)d_in[o + 14];
    p.W2   = (const float*)d_in[o + 15]; p.b2   = (const float*)d_in[o + 16];
    p.W3   = (const float*)d_in[o + 17]; p.b3   = (const float*)d_in[o + 18];
    p.W4   = (const float*)d_in[o + 19]; p.b4   = (const float*)d_in[o + 20];
    p.out  = (float*)d_out;

    cudaFuncSetAttribute(ggnn_main, cudaFuncAttributeMaxDynamicSharedMemorySize,
                         SMEM_FLOATS * (int)sizeof(float));

    ggnn_pre<<<TYPEC + 1, 192>>>(p);
    ggnn_main<<<Bc, NTHR, SMEM_FLOATS * (int)sizeof(float)>>>(p);
}

// round 16
// speedup vs baseline: 1.3313x; 1.0864x over previous
#include <cuda_runtime.h>
#include <cuda_bf16.h>
#include <math.h>

// Problem constants
#define Bc 128
#define Nc 128
#define Ec 64
#define TYPEC 201   // TYPE_NUM+1
#define RELC  51    // REL_NUM+1

#define NTHR 384
#define BAR_B() asm volatile("bar.sync 1, 128;" ::: "memory")

typedef unsigned long long ull;

// ---- Blackwell packed f32x2 helpers (fma/pack/unpack only) ----
__device__ __forceinline__ ull f2fma(ull a, ull b, ull c) {
    ull d; asm("fma.rn.f32x2 %0, %1, %2, %3;" : "=l"(d) : "l"(a), "l"(b), "l"(c)); return d;
}
__device__ __forceinline__ ull packf2(float lo, float hi) {
    ull d; asm("mov.b64 %0, {%1, %2};" : "=l"(d) : "f"(lo), "f"(hi)); return d;
}
__device__ __forceinline__ float2 unpackf2(ull v) {
    float lo, hi; asm("mov.b64 {%0, %1}, %2;" : "=f"(lo), "=f"(hi) : "l"(v));
    return make_float2(lo, hi);
}

// Precomputed batch-independent tables
__device__ float g_typeproj[TYPEC * 192];
__device__ float g_relproj[RELC * 64];

struct GParams {
    const int*   node_slice;
    const int*   type_slice;
    const float* distance;
    const int*   rel_matrix;
    const int*   input_length;
    const float* emb_table;
    const float* type_table;
    const float* rel_table;
    const float* W_in; const float* b_in;
    const float* Wr;   const float* br;
    const float* Wz;   const float* bz;
    const float* Wt;   const float* bt;
    const float* W_co; const float* b_co;
    const float* W1;   const float* b1;
    const float* W2;   const float* b2;
    const float* W3;   const float* b3;
    const float* W4;   const float* b4;
    float* out;
};

// ---------------------------------------------------------------------------
__global__ void ggnn_pre(GParams p) {
    int blk = blockIdx.x;
    int t = threadIdx.x;
    if (blk < TYPEC) {
        if (t < 192) {
            int gate = t >> 6, e = t & 63;
            const float* Wg = (gate == 0) ? p.Wr : ((gate == 1) ? p.Wz : p.Wt);
            const float* bg = (gate == 0) ? p.br : ((gate == 1) ? p.bz : p.bt);
            float acc = bg[e];
            #pragma unroll
            for (int k = 0; k < 32; k++)
                acc += p.type_table[blk * 32 + k] * Wg[k * 64 + e];
            g_typeproj[blk * 192 + t] = acc;
        }
    } else {
        if (t < 64) {
            for (int v = 0; v < RELC; v++) {
                float acc = 0.f;
                #pragma unroll
                for (int k = 0; k < 32; k++)
                    acc += p.rel_table[v * 32 + k] * p.W_in[(64 + k) * 64 + t];
                g_relproj[v * 64 + t] = acc;
            }
        }
    }
}

// ---------------------------------------------------------------------------
// Shared layout (float offsets) — identical to R15
// ---------------------------------------------------------------------------
#define SM_HD    0        // 8192 : (hidden@W_h + b_in) * disc[row]
#define SM_HID   8192     // 8192 : raw hidden state
#define SM_NP    16384    // 24576
#define SM_RP    40960    // 3264 (row 0 = +1e30 sentinel), pad to 3328
#define SM_DISC  44288    // 128
#define SM_PBUF  44416    // 2 * 9 * 64 = 1152 (8 A slots + 1 corr slot)
#define SM_DP    45568    // 64
#define SM_RD    45632    // 64 : r * dis_pre
#define SM_Z     45696    // 64 : z gate scratch
#define SM_NR    45760    // 64
#define SM_BIN   45824    // 64
#define SM_RV    45888    // 3*128 ints : rel row ring
#define SM_TV    46272    // 128 ints
#define SM_CORRV 46400    // 3 ints (pad 64)
#define SM_FIN   46464    // 768
#define SM_STAGE 47232    // 8192 (init GEMM staging)
#define SMEM_FLOATS 55424

__global__ void __launch_bounds__(NTHR, 1) ggnn_main(GParams p) {
    extern __shared__ float S[];
    const int t = threadIdx.x;
    const int b = blockIdx.x;
    int* rvs = (int*)&S[SM_RV];
    int* tvs = (int*)&S[SM_TV];
    int* corrv = (int*)&S[SM_CORRV];
    const int len = p.input_length[b];
    const int* relrow = p.rel_matrix + (long long)b * Nc * Nc;

    // ---------------- init gathers ----------------
    {
        const float4* emb4 = (const float4*)p.emb_table;
        float4* hid4 = (float4*)&S[SM_HID];
        for (int idx = t; idx < Nc * 16; idx += NTHR) {
            int j = idx >> 4, q = idx & 15;
            long long nd = p.node_slice[b * Nc + j];
            hid4[idx] = emb4[nd * 16 + q];
        }
    }
    if (t < 128) {
        S[SM_DISC + t] = -0.1f * p.distance[b * Nc + t];
        tvs[t] = p.type_slice[b * Nc + t];
        rvs[t] = (t < len) ? relrow[t] : 0;      // ring slot 0, len-masked
    }
    for (int idx = t; idx < RELC * 64; idx += NTHR) S[SM_RP + idx] = g_relproj[idx];
    if (t < 64) {
        S[SM_RP + t] = 1e30f;                    // sentinel row: rv==0 -> s ~ -1e29
        S[SM_BIN + t] = p.b_in[t];
        S[SM_PBUF + 512 + t] = -1e30f;           // corr slot of buffer 0
    }

    // ---- persistent PACKED gate weights in registers (group B, 128 regs) ----
    // wRZ2[32]: this thread's gate (r if half==0, z if half==1), FULL k-range.
    // wX2[32] : threads u<64 hold Wt (full k) for e=u; threads u>=64 hold
    //           W_in/W_h (full k) for e=u-64. Thread-disjoint contents, one array.
    ull wRZ2[32], wX2[32];
    if (t >= 256) {
        int u = t - 256;
        int e = u >> 1, half = u & 1;
        const float* Wg = half ? p.Wz : p.Wr;
        #pragma unroll
        for (int c = 0; c < 32; c++)
            wRZ2[c] = packf2(Wg[(96 + 2 * c) * 64 + e], Wg[(96 + 2 * c + 1) * 64 + e]);
        int e_own = u & 63;
        const float* Wsrc = (u < 64) ? (p.Wt + 96 * 64) : p.W_in;
        #pragma unroll
        for (int c = 0; c < 32; c++)
            wX2[c] = packf2(Wsrc[(2 * c) * 64 + e_own], Wsrc[(2 * c + 1) * 64 + e_own]);
    }
    __syncthreads();

    // ---------------- HD init: HD = (hidden @ W_h + b_in) * disc ----------------
    for (int idx = t; idx < 4096; idx += NTHR) S[SM_STAGE + idx] = p.W_in[idx];
    __syncthreads();
    for (int x = t; x < 512; x += NTHR) {
        int j0 = (x >> 4) << 2, e0 = (x & 15) << 2;
        float acc[4][4];
        #pragma unroll
        for (int m = 0; m < 4; m++)
            #pragma unroll
            for (int n = 0; n < 4; n++) acc[m][n] = S[SM_BIN + e0 + n];
        #pragma unroll 4
        for (int k = 0; k < 64; k++) {
            float4 w = *(const float4*)&S[SM_STAGE + k * 64 + e0];
            #pragma unroll
            for (int m = 0; m < 4; m++) {
                float h = S[SM_HID + (j0 + m) * 64 + k];
                acc[m][0] += h * w.x; acc[m][1] += h * w.y;
                acc[m][2] += h * w.z; acc[m][3] += h * w.w;
            }
        }
        #pragma unroll
        for (int m = 0; m < 4; m++) {
            float d = S[SM_DISC + j0 + m];
            #pragma unroll
            for (int n = 0; n < 4; n++)
                S[SM_HD + (j0 + m) * 64 + e0 + n] = acc[m][n] * d;
        }
    }
    __syncthreads();

    // -------- now_part: typeproj[tv] + node_emb @ Wg[32:96] --------
    for (int idx = t; idx < 8192; idx += NTHR) {
        int k = idx >> 7, c = idx & 127;
        S[SM_STAGE + idx] = (c < 64) ? p.Wr[(32 + k) * 64 + c]
                                     : p.Wz[(32 + k) * 64 + (c - 64)];
    }
    __syncthreads();
    for (int x = t; x < 1024; x += NTHR) {
        int i0 = (x >> 5) << 2, c0 = (x & 31) << 2;
        float acc[4][4];
        #pragma unroll
        for (int m = 0; m < 4; m++) {
            const float* tp = &g_typeproj[tvs[i0 + m] * 192 + c0];
            acc[m][0] = tp[0]; acc[m][1] = tp[1]; acc[m][2] = tp[2]; acc[m][3] = tp[3];
        }
        #pragma unroll 4
        for (int k = 0; k < 64; k++) {
            float4 w = *(const float4*)&S[SM_STAGE + k * 128 + c0];
            #pragma unroll
            for (int m = 0; m < 4; m++) {
                float h = S[SM_HID + (i0 + m) * 64 + k];
                acc[m][0] += h * w.x; acc[m][1] += h * w.y;
                acc[m][2] += h * w.z; acc[m][3] += h * w.w;
            }
        }
        #pragma unroll
        for (int m = 0; m < 4; m++)
            #pragma unroll
            for (int n = 0; n < 4; n++)
                S[SM_NP + (i0 + m) * 192 + c0 + n] = acc[m][n];
    }
    __syncthreads();
    for (int idx = t; idx < 4096; idx += NTHR) {
        int k = idx >> 6, e = idx & 63;
        S[SM_STAGE + idx] = p.Wt[(32 + k) * 64 + e];
    }
    __syncthreads();
    for (int x = t; x < 512; x += NTHR) {
        int i0 = (x >> 4) << 2, e0 = (x & 15) << 2;
        float acc[4][4];
        #pragma unroll
        for (int m = 0; m < 4; m++) {
            const float* tp = &g_typeproj[tvs[i0 + m] * 192 + 128 + e0];
            acc[m][0] = tp[0]; acc[m][1] = tp[1]; acc[m][2] = tp[2]; acc[m][3] = tp[3];
        }
        #pragma unroll 4
        for (int k = 0; k < 64; k++) {
            float4 w = *(const float4*)&S[SM_STAGE + k * 64 + e0];
            #pragma unroll
            for (int m = 0; m < 4; m++) {
                float h = S[SM_HID + (i0 + m) * 64 + k];
                acc[m][0] += h * w.x; acc[m][1] += h * w.y;
                acc[m][2] += h * w.z; acc[m][3] += h * w.w;
            }
        }
        #pragma unroll
        for (int m = 0; m < 4; m++)
            #pragma unroll
            for (int n = 0; n < 4; n++)
                S[SM_NP + (i0 + m) * 192 + 128 + e0 + n] = acc[m][n];
    }
    __syncthreads();

    // ---------------- pipelined scan ----------------
    // iter i: A (t<256, 8 warps) computes max_j f32x2-fma(rp, d, hd) partials
    // for step i+1; B (t>=256, 4 warps): 9-max+clamp -> r|z (split by gate,
    // no shfl) -> hhat+update (u<64, full-k, no shfl) -> HD+corr (u>=64,
    // full-k, no shfl).
    const int lane = t & 31, w5 = t >> 5;
    const int gA = t >> 4;                      // 0..15 (j base) for A
    const int e4 = (t & 15) << 2;               // 0..60
    for (int i = -1; i < Nc; i++) {
        if (t < 256) {
            int rv_pref = 0;
            bool do_pref = (t < 128) && (i + 2 < Nc);
            if (do_pref) rv_pref = relrow[(i + 2) * Nc + t];
            if (i < Nc - 1) {
                const int s = i + 1;
                const int* rv = rvs + (s % 3) * 128;
                float a0 = -1e30f, a1 = -1e30f, a2 = -1e30f, a3 = -1e30f;
                #pragma unroll
                for (int jj = 0; jj < 8; jj++) {
                    int j = gA + (jj << 4);
                    int rvj = rv[j];
                    float d = S[SM_DISC + j];
                    ull d2 = packf2(d, d);
                    ulonglong2 hd = *(const ulonglong2*)&S[SM_HD + j * 64 + e4];
                    ulonglong2 rp = *(const ulonglong2*)&S[SM_RP + rvj * 64 + e4];
                    float2 u0 = unpackf2(f2fma(rp.x, d2, hd.x));
                    float2 u1 = unpackf2(f2fma(rp.y, d2, hd.y));
                    a0 = fmaxf(a0, u0.x); a1 = fmaxf(a1, u0.y);
                    a2 = fmaxf(a2, u1.x); a3 = fmaxf(a3, u1.y);
                }
                a0 = fmaxf(a0, __shfl_xor_sync(0xffffffffu, a0, 16));
                a1 = fmaxf(a1, __shfl_xor_sync(0xffffffffu, a1, 16));
                a2 = fmaxf(a2, __shfl_xor_sync(0xffffffffu, a2, 16));
                a3 = fmaxf(a3, __shfl_xor_sync(0xffffffffu, a3, 16));
                if (lane < 16)
                    *(float4*)&S[SM_PBUF + (s & 1) * 576 + w5 * 64 + e4] =
                        make_float4(a0, a1, a2, a3);
            }
            if (do_pref) {
                int val = (t < len) ? rv_pref : 0;
                int ring2 = (i + 2) % 3;
                if (t == i + 1) { corrv[ring2] = val; val = 0; }  // excluded -> side
                rvs[ring2 * 128 + t] = val;
            }
        } else if (i >= 0) {
            const int u = t - 256;               // 0..127
            const int e = u >> 1, half = u & 1;
            // P0: 9-way max -> clamp -> dis_pre
            if (u < 64) {
                float m = S[SM_PBUF + (i & 1) * 576 + u];
                #pragma unroll
                for (int s2 = 1; s2 < 9; s2++)
                    m = fmaxf(m, S[SM_PBUF + (i & 1) * 576 + s2 * 64 + u]);
                S[SM_DP + u] = (m < -5e28f) ? 0.f : fminf(m, 0.f);
            }
            BAR_B();
            // P1: r (half==0) / z (half==1), full-k per thread, no shfl
            {
                float dp_e = S[SM_DP + e];                       // early
                float np = S[SM_NP + i * 192 + half * 64 + e];   // early
                const ulonglong2* dp2 = (const ulonglong2*)&S[SM_DP];
                ull a0 = 0, a1 = 0, a2 = 0, a3 = 0;
                #pragma unroll
                for (int c = 0; c < 8; c++) {
                    ulonglong2 dA = dp2[2 * c], dB = dp2[2 * c + 1];
                    a0 = f2fma(wRZ2[4 * c + 0], dA.x, a0);
                    a1 = f2fma(wRZ2[4 * c + 1], dA.y, a1);
                    a2 = f2fma(wRZ2[4 * c + 2], dB.x, a2);
                    a3 = f2fma(wRZ2[4 * c + 3], dB.y, a3);
                }
                float2 q0 = unpackf2(a0), q1 = unpackf2(a1);
                float2 q2 = unpackf2(a2), q3 = unpackf2(a3);
                float sum = ((q0.x + q0.y) + (q1.x + q1.y))
                          + ((q2.x + q2.y) + (q3.x + q3.y));
                float ex = __expf(-(np + sum));
                float g = __fdividef(1.0f, 1.0f + ex);
                if (half == 0) S[SM_RD + e] = g * dp_e;
                else           S[SM_Z + e] = g;
            }
            BAR_B();
            // P2: h_hat + GRU update — threads u<64 own e=u, full-k, no shfl
            if (u < 64) {
                const int eo = u;
                float np_t = S[SM_NP + i * 192 + 128 + eo];       // early
                float hid_old = S[SM_HID + i * 64 + eo];          // early
                float dp_e = S[SM_DP + eo];                       // early
                float z_e = S[SM_Z + eo];                         // early
                const ulonglong2* rd2 = (const ulonglong2*)&S[SM_RD];
                ull a0 = 0, a1 = 0, a2 = 0, a3 = 0;
                #pragma unroll
                for (int c = 0; c < 8; c++) {
                    ulonglong2 dA = rd2[2 * c], dB = rd2[2 * c + 1];
                    a0 = f2fma(wX2[4 * c + 0], dA.x, a0);
                    a1 = f2fma(wX2[4 * c + 1], dA.y, a1);
                    a2 = f2fma(wX2[4 * c + 2], dB.x, a2);
                    a3 = f2fma(wX2[4 * c + 3], dB.y, a3);
                }
                float2 q0 = unpackf2(a0), q1 = unpackf2(a1);
                float2 q2 = unpackf2(a2), q3 = unpackf2(a3);
                float sum = ((q0.x + q0.y) + (q1.x + q1.y))
                          + ((q2.x + q2.y) + (q3.x + q3.y));
                float v = np_t + sum;
                float ex = __expf(2.f * v);
                float hh = 1.f - __fdividef(2.f, ex + 1.f);   // tanh, overflow-safe
                float up = (1.0f - z_e) * dp_e + z_e * hh;
                float nr = (i < len) ? up : hid_old;
                S[SM_HID + i * 64 + eo] = nr;
                S[SM_NR + eo] = nr;
            }
            BAR_B();
            // P3: HD row refresh + corr — threads u>=64 own e=u-64, full-k, no shfl
            if (u >= 64) {
                const int eo = u - 64;
                float di = S[SM_DISC + i];                        // early
                float bin_e = S[SM_BIN + eo];                     // early
                int vcorr = 0; float rp_c = 0.f;
                if (i + 1 < Nc) {
                    vcorr = corrv[(i + 1) % 3];
                    rp_c = S[SM_RP + vcorr * 64 + eo];
                }
                const ulonglong2* n2 = (const ulonglong2*)&S[SM_NR];
                ull a0 = 0, a1 = 0, a2 = 0, a3 = 0;
                #pragma unroll
                for (int c = 0; c < 8; c++) {
                    ulonglong2 nA = n2[2 * c], nB = n2[2 * c + 1];
                    a0 = f2fma(wX2[4 * c + 0], nA.x, a0);
                    a1 = f2fma(wX2[4 * c + 1], nA.y, a1);
                    a2 = f2fma(wX2[4 * c + 2], nB.x, a2);
                    a3 = f2fma(wX2[4 * c + 3], nB.y, a3);
                }
                float2 q0 = unpackf2(a0), q1 = unpackf2(a1);
                float2 q2 = unpackf2(a2), q3 = unpackf2(a3);
                float sum = ((q0.x + q0.y) + (q1.x + q1.y))
                          + ((q2.x + q2.y) + (q3.x + q3.y));
                float hd = (bin_e + sum) * di;
                S[SM_HD + i * 64 + eo] = hd;
                if (i + 1 < Nc) {
                    float c = (vcorr != 0) ? fmaf(rp_c, di, hd) : -1e30f;
                    S[SM_PBUF + ((i + 1) & 1) * 576 + 512 + eo] = c;
                }
            }
        }
        __syncthreads();
    }

    // ---------------- final head ----------------
    for (int x = t; x < 512; x += NTHR) {
        int tE = x & 63, tJG = x >> 6;
        float acc = -1e30f;
        #pragma unroll
        for (int jj = 0; jj < 16; jj++) {
            int j = tJG + (jj << 3);
            if (j < len) acc = fmaxf(acc, S[SM_HID + j * 64 + tE]);
        }
        S[SM_PBUF + tJG * 64 + tE] = acc;
    }
    __syncthreads();
    if (t < 64) {
        float m = S[SM_PBUF + t];
        #pragma unroll
        for (int g = 1; g < 8; g++) m = fmaxf(m, S[SM_PBUF + g * 64 + t]);
        S[SM_FIN + 128 + t] = m;                               // sub
        S[SM_FIN + t]       = S[SM_HID + t];                   // user
        S[SM_FIN + 64 + t]  = S[SM_HID + (len - 1) * 64 + t];  // item
    }
    __syncthreads();
    if (t < 128) {  // ua / ia
        int which = t >> 6, e = t & 63;
        const float* first = which ? &S[SM_FIN + 64] : &S[SM_FIN];
        float acc = p.b_co[e];
        #pragma unroll 4
        for (int k = 0; k < 64; k++) acc += first[k] * p.W_co[k * 64 + e];
        #pragma unroll 4
        for (int k = 0; k < 64; k++) acc += S[SM_FIN + 128 + k] * p.W_co[(64 + k) * 64 + e];
        S[SM_FIN + 192 + which * 64 + e] = fmaxf(acc, 0.f);
    }
    __syncthreads();
    if (t < 192) {  // temp = [ua*user, sub, ia*item]
        float v;
        if (t < 64)       v = S[SM_FIN + 192 + t] * S[SM_FIN + t];
        else if (t < 128) v = S[SM_FIN + 128 + (t - 64)];
        else              v = S[SM_FIN + 256 + (t - 128)] * S[SM_FIN + 64 + (t - 128)];
        S[SM_FIN + 320 + t] = v;
    }
    __syncthreads();
    if (t < 128) {
        float acc = p.b1[t];
        #pragma unroll 4
        for (int k = 0; k < 192; k++) acc += S[SM_FIN + 320 + k] * p.W1[k * 128 + t];
        S[SM_FIN + 512 + t] = fmaxf(acc, 0.f);
    }
    __syncthreads();
    if (t < 64) {
        float acc = p.b2[t];
        #pragma unroll 4
        for (int k = 0; k < 128; k++) acc += S[SM_FIN + 512 + k] * p.W2[k * 64 + t];
        S[SM_FIN + 640 + t] = fmaxf(acc, 0.f);
    }
    __syncthreads();
    if (t < 32) {
        float acc = p.b3[t];
        #pragma unroll 4
        for (int k = 0; k < 64; k++) acc += S[SM_FIN + 640 + k] * p.W3[k * 32 + t];
        S[SM_FIN + 704 + t] = fmaxf(acc, 0.f);
    }
    __syncthreads();
    if (t == 0) {
        float acc = p.b4[0];
        #pragma unroll
        for (int k = 0; k < 32; k++) acc += S[SM_FIN + 704 + k] * p.W4[k];
        p.out[b] = __fdividef(1.0f, 1.0f + __expf(-acc));
    }
}

// ---------------------------------------------------------------------------
extern "C" void kernel_launch(void* const* d_in, const int* in_sizes, int n_in,
                              void* d_out, int out_size) {
    GParams p;
    p.node_slice   = (const int*)d_in[0];
    p.type_slice   = (const int*)d_in[1];
    p.distance     = (const float*)d_in[2];
    p.rel_matrix   = (const int*)d_in[3];
    p.input_length = (const int*)d_in[4];
    int o = (n_in >= 27) ? 6 : 5;
    p.emb_table  = (const float*)d_in[o + 0];
    p.type_table = (const float*)d_in[o + 1];
    p.rel_table  = (const float*)d_in[o + 2];
    p.W_in = (const float*)d_in[o + 3];  p.b_in = (const float*)d_in[o + 4];
    p.Wr   = (const float*)d_in[o + 5];  p.br   = (const float*)d_in[o + 6];
    p.Wz   = (const float*)d_in[o + 7];  p.bz   = (const float*)d_in[o + 8];
    p.Wt   = (const float*)d_in[o + 9];  p.bt   = (const float*)d_in[o + 10];
    p.W_co = (const float*)d_in[o + 11]; p.b_co = (const float*)d_in[o + 12];
    p.W1   = (const float*)d_in[o + 13]; p.b1   = (const float*)d_in[o + 14];
    p.W2   = (const float*)d_in[o + 15]; p.b2   = (const float*)d_in[o + 16];
    p.W3   = (const float*)d_in[o + 17]; p.b3   = (const float*)d_in[o + 18];
    p.W4   = (const float*)d_in[o + 19]; p.b4   = (const float*)d_in[o + 20];
    p.out  = (float*)d_out;

    cudaFuncSetAttribute(ggnn_main, cudaFuncAttributeMaxDynamicSharedMemorySize,
                         SMEM_FLOATS * (int)sizeof(float));

    ggnn_pre<<<TYPEC + 1, 192>>>(p);
    ggnn_main<<<Bc, NTHR, SMEM_FLOATS * (int)sizeof(float)>>>(p);
}